// round 3
// baseline (speedup 1.0000x reference)
#include <cuda_runtime.h>

#define NB   64      // batch
#define NT   1024    // timesteps
#define NIN  256     // input dim
#define NH   512     // hidden dim
#define NCTA 128     // 16 batch-blocks x 8 col-blocks
#define NTHR 256
#define NGRP 16      // independent barrier groups (one per batch-block)
#define GSZ  8       // CTAs per group

#define WST  68      // Wsm row stride (floats): 64 + 4 pad -> conflict-free
#define CST  68      // red row stride per batch row
#define RST  272     // red per-partial stride: 4*68

// ---------------- device globals (scratch; no allocations allowed) ----------
__device__ unsigned g_bars[NGRP * 32];        // one counter per 128B
__device__ float    g_fr[2][NH * NB];         // [hid][batch]

__global__ void init_kernel() {
    if (threadIdx.x < NGRP) g_bars[threadIdx.x * 32] = 0u;
}

// ---------------- Phase A: v_in = x @ W_in + b_in  -> written into d_out ----
#define BM 64
#define BN 64
#define BK 16

__global__ __launch_bounds__(256) void gemm_vin(const float* __restrict__ A,
                                                const float* __restrict__ Bm,
                                                const float* __restrict__ bias,
                                                float* __restrict__ C) {
    __shared__ float As[BK][BM + 4];
    __shared__ float Bs[BK][BN];
    const int tid = threadIdx.x;
    const int m0 = blockIdx.y * BM;
    const int n0 = blockIdx.x * BN;
    const int tx = tid & 15;
    const int ty = tid >> 4;

    float acc[4][4];
#pragma unroll
    for (int i = 0; i < 4; ++i)
#pragma unroll
        for (int j = 0; j < 4; ++j) acc[i][j] = 0.f;

    for (int k0 = 0; k0 < NIN; k0 += BK) {
        // A tile 64x16 -> transposed store
#pragma unroll
        for (int i = tid; i < BM * BK / 4; i += 256) {
            int m = i >> 2, kq = i & 3;
            float4 v = *(const float4*)(A + (long)(m0 + m) * NIN + k0 + kq * 4);
            As[kq * 4 + 0][m] = v.x;
            As[kq * 4 + 1][m] = v.y;
            As[kq * 4 + 2][m] = v.z;
            As[kq * 4 + 3][m] = v.w;
        }
#pragma unroll
        for (int i = tid; i < BK * BN / 4; i += 256) {
            int kk = i >> 4, nq = i & 15;
            *(float4*)(&Bs[kk][nq * 4]) =
                *(const float4*)(Bm + (long)(k0 + kk) * NH + n0 + nq * 4);
        }
        __syncthreads();

#pragma unroll
        for (int kk = 0; kk < BK; ++kk) {
            float4 a4 = *(const float4*)(&As[kk][ty * 4]);
            float4 b4 = *(const float4*)(&Bs[kk][tx * 4]);
            acc[0][0] = fmaf(a4.x, b4.x, acc[0][0]);
            acc[0][1] = fmaf(a4.x, b4.y, acc[0][1]);
            acc[0][2] = fmaf(a4.x, b4.z, acc[0][2]);
            acc[0][3] = fmaf(a4.x, b4.w, acc[0][3]);
            acc[1][0] = fmaf(a4.y, b4.x, acc[1][0]);
            acc[1][1] = fmaf(a4.y, b4.y, acc[1][1]);
            acc[1][2] = fmaf(a4.y, b4.z, acc[1][2]);
            acc[1][3] = fmaf(a4.y, b4.w, acc[1][3]);
            acc[2][0] = fmaf(a4.z, b4.x, acc[2][0]);
            acc[2][1] = fmaf(a4.z, b4.y, acc[2][1]);
            acc[2][2] = fmaf(a4.z, b4.z, acc[2][2]);
            acc[2][3] = fmaf(a4.z, b4.w, acc[2][3]);
            acc[3][0] = fmaf(a4.w, b4.x, acc[3][0]);
            acc[3][1] = fmaf(a4.w, b4.y, acc[3][1]);
            acc[3][2] = fmaf(a4.w, b4.z, acc[3][2]);
            acc[3][3] = fmaf(a4.w, b4.w, acc[3][3]);
        }
        __syncthreads();
    }

#pragma unroll
    for (int i = 0; i < 4; ++i) {
        const int m = m0 + ty * 4 + i;
#pragma unroll
        for (int j = 0; j < 4; ++j) {
            const int n = n0 + tx * 4 + j;
            C[(long)m * NH + n] = acc[i][j] + bias[n];
        }
    }
}

// ---------------- Phase B: persistent recurrent kernel ----------------------
// 16 batch-blocks (4 batches) x 8 col-blocks (64 cols). Batches are
// independent in the recurrence -> barrier only among the 8 CTAs sharing a
// batch-block. Staging is 8KB/CTA (2 LDG.128 per thread). Register tiling:
// thread (kt 0..15, cg 0..15) computes 4b x 4c partials on K-slice kt;
// shfl_xor(16) pairs kt, SMEM reduce folds 8.

#define ROWFMA(accv, s, w)                          \
    accv.x = fmaf(s, w.x, accv.x);                  \
    accv.y = fmaf(s, w.y, accv.y);                  \
    accv.z = fmaf(s, w.z, accv.z);                  \
    accv.w = fmaf(s, w.w, accv.w);

__global__ __launch_bounds__(NTHR, 1) void step_kernel(
    const float* __restrict__ W_hid,
    const float* __restrict__ b_hid,
    const float* __restrict__ alpha,
    const float* __restrict__ init_state,
    float* __restrict__ out) {
    extern __shared__ float sh[];
    float* Wsm = sh;                       // [NH][WST]   k-major, 64 cols
    float* frs = sh + NH * WST;            // [NH][4]     k-major, 4 batches
    float* red = sh + NH * WST + NH * 4;   // [8][RST]

    const int tid = threadIdx.x;
    const int bb  = blockIdx.x >> 3;       // 0..15  (batch block / group)
    const int cb  = blockIdx.x & 7;        // 0..7   (col block)
    const int B0  = bb * 4;
    const int C0  = cb * 64;
    unsigned* bar = &g_bars[bb * 32];

    // compute-role ids
    const int kt = tid >> 4;               // 0..15 (K slice)
    const int cg = tid & 15;               // 0..15 (col quad)
    // epilogue-role ids
    const int eb = tid >> 6;               // 0..3
    const int ec = tid & 63;               // 0..63
    const int gb = B0 + eb;
    const int gc = C0 + ec;

    // one-time W slice: Wsm[k][c] = W_hid[k][C0+c]
    for (int i = tid; i < NH * 16; i += NTHR) {      // float4 granules
        int k = i >> 4, cq = i & 15;
        *(float4*)(Wsm + k * WST + cq * 4) =
            *(const float4*)(W_hid + (long)k * NH + C0 + cq * 4);
    }

    // init state
    float v  = init_state[gb * NH + gc];
    float fr = fmaxf(v, 0.f);
    __stcg(&g_fr[0][gc * NB + gb], fr);
    const float al  = alpha[gc];
    const float bh  = b_hid[gc];
    const float oma = 1.f - al;

    unsigned epoch = 1;
    // initial group barrier: g_fr[0] + Wsm ready within group
    __syncthreads();
    if (tid == 0) {
        __threadfence();
        atomicAdd(bar, 1u);
        while (*((volatile unsigned*)bar) < epoch * GSZ) { }
        __threadfence();
    }
    __syncthreads();

    const float* fbase = frs + kt * 4;
    const float* wbase = Wsm + kt * WST + cg * 4;

    int p = 0;
    for (int t = 0; t < NT; ++t) {
        const long oidx = ((long)gb * NT + t) * NH + gc;
        const float vin = out[oidx];       // prefetch (DRAM), hidden under stage+FMA

        // stage fr(t-1): frs[k][0..3] = g_fr[p][k][B0..B0+3]  (2 LDG.128/thread)
        {
            const float* src = &g_fr[p][B0];
            float4 v0 = __ldcg((const float4*)(src + (long)tid * NB));
            float4 v1 = __ldcg((const float4*)(src + (long)(tid + 256) * NB));
            *(float4*)(frs + tid * 4)         = v0;
            *(float4*)(frs + (tid + 256) * 4) = v1;
        }
        __syncthreads();

        // register-tiled partial GEMM over K slice: k = it*16 + kt
        float4 acc0 = {0,0,0,0}, acc1 = {0,0,0,0}, acc2 = {0,0,0,0}, acc3 = {0,0,0,0};
#pragma unroll 8
        for (int it = 0; it < 32; ++it) {
            const int koff = it * 16;
            float4 f = *(const float4*)(fbase + koff * 4);
            float4 w = *(const float4*)(wbase + koff * WST);
            ROWFMA(acc0, f.x, w);
            ROWFMA(acc1, f.y, w);
            ROWFMA(acc2, f.z, w);
            ROWFMA(acc3, f.w, w);
        }

        // pair-reduce kt with kt^1 (lanes differ by 16 within warp)
        acc0.x += __shfl_xor_sync(0xffffffffu, acc0.x, 16);
        acc0.y += __shfl_xor_sync(0xffffffffu, acc0.y, 16);
        acc0.z += __shfl_xor_sync(0xffffffffu, acc0.z, 16);
        acc0.w += __shfl_xor_sync(0xffffffffu, acc0.w, 16);
        acc1.x += __shfl_xor_sync(0xffffffffu, acc1.x, 16);
        acc1.y += __shfl_xor_sync(0xffffffffu, acc1.y, 16);
        acc1.z += __shfl_xor_sync(0xffffffffu, acc1.z, 16);
        acc1.w += __shfl_xor_sync(0xffffffffu, acc1.w, 16);
        acc2.x += __shfl_xor_sync(0xffffffffu, acc2.x, 16);
        acc2.y += __shfl_xor_sync(0xffffffffu, acc2.y, 16);
        acc2.z += __shfl_xor_sync(0xffffffffu, acc2.z, 16);
        acc2.w += __shfl_xor_sync(0xffffffffu, acc2.w, 16);
        acc3.x += __shfl_xor_sync(0xffffffffu, acc3.x, 16);
        acc3.y += __shfl_xor_sync(0xffffffffu, acc3.y, 16);
        acc3.z += __shfl_xor_sync(0xffffffffu, acc3.z, 16);
        acc3.w += __shfl_xor_sync(0xffffffffu, acc3.w, 16);

        if ((kt & 1) == 0) {
            float* rp = red + (kt >> 1) * RST + cg * 4;
            *(float4*)(rp + 0 * CST) = acc0;
            *(float4*)(rp + 1 * CST) = acc1;
            *(float4*)(rp + 2 * CST) = acc2;
            *(float4*)(rp + 3 * CST) = acc3;
        }
        __syncthreads();

        // final reduce + leaky-integrator update
        float s = 0.f;
#pragma unroll
        for (int r = 0; r < 8; ++r)
            s += red[r * RST + eb * CST + ec];

        v  = oma * v + al * (s + bh + vin);
        fr = fmaxf(v, 0.f);
        __stcg(&g_fr[p ^ 1][gc * NB + gb], fr);

        // group barrier: arrive early, hide out-store under peers' arrival
        ++epoch;
        __syncthreads();
        if (tid == 0) {
            __threadfence();
            atomicAdd(bar, 1u);
        }
        out[oidx] = fr;                    // not barrier-protected (self-owned)
        if (tid == 0) {
            while (*((volatile unsigned*)bar) < epoch * GSZ) { }
            __threadfence();
        }
        __syncthreads();
        p ^= 1;
    }
}

// ---------------- launch ----------------------------------------------------
extern "C" void kernel_launch(void* const* d_in, const int* in_sizes, int n_in,
                              void* d_out, int out_size) {
    const float* x     = (const float*)d_in[0];
    const float* init  = (const float*)d_in[1];
    const float* W_in  = (const float*)d_in[2];
    const float* b_in  = (const float*)d_in[3];
    const float* W_hid = (const float*)d_in[4];
    const float* b_hid = (const float*)d_in[5];
    const float* alpha = (const float*)d_in[6];
    float* out = (float*)d_out;

    const int smem = (NH * WST + NH * 4 + 8 * RST) * (int)sizeof(float); // ~153KB
    cudaFuncSetAttribute(step_kernel, cudaFuncAttributeMaxDynamicSharedMemorySize, smem);

    init_kernel<<<1, 32>>>();

    dim3 grid(NH / BN, (NB * NT) / BM);   // (8, 1024)
    gemm_vin<<<grid, 256>>>(x, W_in, b_in, out);

    step_kernel<<<NCTA, NTHR, smem>>>(W_hid, b_hid, alpha, init, out);
}